// round 10
// baseline (speedup 1.0000x reference)
#include <cuda_runtime.h>
#include <math.h>
#include <stdint.h>

// ---------------------------------------------------------------------------
#define FDIM 128
#define DDEG 16
#define KH   2048
#define ODIM 256
#define JS   16
#define JCH  (KH/JS)

// Scratch (device globals; no allocation allowed)
__device__ float g_Mpart[JS][2][FDIM][ODIM];        // 4 MB partials
__device__ __align__(16) char  g_B1[ODIM * 256];    // B level-1 int8 [o][k]
__device__ __align__(16) char  g_B2[ODIM * 256];    // B level-2 int8 [o][k]
__device__ float g_sbB[ODIM];                       // per-o scale

// ---------------------------------------------------------------------------
// Kernel A: partial M[m][f][o] over a 128-wide j chunk (~14us)
// ---------------------------------------------------------------------------
__global__ void __launch_bounds__(256)
kA(const float* __restrict__ R, const float* __restrict__ Ws,
   const float* __restrict__ Wn)
{
    __shared__ float sA[32][68];
    __shared__ float sB[32][68];

    const int ft = blockIdx.x, ot = blockIdx.y, mz = blockIdx.z;
    const int m = mz / JS, jc = mz % JS;
    const float* __restrict__ W = m ? Wn : Ws;
    const int f0 = ft * 64, o0 = ot * 64;
    const int jbase = jc * JCH;
    const int kk = jbase >> 8, hb = jbase & 255;
    const int tid = threadIdx.x, tx = tid & 15, ty = tid >> 4;

    float acc[4][4];
    #pragma unroll
    for (int i = 0; i < 4; i++)
        #pragma unroll
        for (int j = 0; j < 4; j++) acc[i][j] = 0.f;

    for (int jt = 0; jt < JCH; jt += 32) {
        #pragma unroll
        for (int r = 0; r < 2; r++) {
            int li = tid + r * 256;
            int f_l = li >> 3, jj = (li & 7) * 4;
            float4 a4 = *(const float4*)(R + (size_t)kk * (FDIM * 256)
                                           + (size_t)(f0 + f_l) * 256 + hb + jt + jj);
            sA[jj + 0][f_l] = a4.x; sA[jj + 1][f_l] = a4.y;
            sA[jj + 2][f_l] = a4.z; sA[jj + 3][f_l] = a4.w;
        }
        #pragma unroll
        for (int r = 0; r < 2; r++) {
            int li = tid + r * 256;
            int o_l = li >> 3, jj = (li & 7) * 4;
            float4 b4 = *(const float4*)(W + (size_t)(o0 + o_l) * KH + jbase + jt + jj);
            sB[jj + 0][o_l] = b4.x; sB[jj + 1][o_l] = b4.y;
            sB[jj + 2][o_l] = b4.z; sB[jj + 3][o_l] = b4.w;
        }
        __syncthreads();
        #pragma unroll
        for (int jj = 0; jj < 32; jj++) {
            float4 a4 = *(const float4*)&sA[jj][ty * 4];
            float4 b4 = *(const float4*)&sB[jj][tx * 4];
            float a[4] = {a4.x, a4.y, a4.z, a4.w};
            float b[4] = {b4.x, b4.y, b4.z, b4.w};
            #pragma unroll
            for (int i = 0; i < 4; i++)
                #pragma unroll
                for (int j = 0; j < 4; j++) acc[i][j] += a[i] * b[j];
        }
        __syncthreads();
    }
    float* outp = &g_Mpart[jc][m][0][0];
    #pragma unroll
    for (int i = 0; i < 4; i++) {
        float4 v = make_float4(acc[i][0], acc[i][1], acc[i][2], acc[i][3]);
        *(float4*)(outp + (size_t)(f0 + ty * 4 + i) * ODIM + o0 + tx * 4) = v;
    }
}

// ---------------------------------------------------------------------------
// kReduceQ: reduce partials; per-o two-level int8 quantization of B[o][k].
// grid 256 (one block per o), block 256 (one thread per k).
// ---------------------------------------------------------------------------
__global__ void __launch_bounds__(256)
kReduceQ()
{
    const int o = blockIdx.x, k = threadIdx.x;
    const int m = k >> 7, f = k & 127;
    const float* p = (const float*)g_Mpart;
    float s = 0.f;
    #pragma unroll
    for (int q = 0; q < JS; q++)
        s += p[q * 65536 + m * 32768 + f * 256 + o];

    __shared__ float red[8];
    float v = fabsf(s);
    #pragma unroll
    for (int off = 16; off; off >>= 1)
        v = fmaxf(v, __shfl_xor_sync(0xFFFFFFFFu, v, off));
    if ((k & 31) == 0) red[k >> 5] = v;
    __syncthreads();
    float vmax = red[0];
    #pragma unroll
    for (int i = 1; i < 8; i++) vmax = fmaxf(vmax, red[i]);
    vmax = fmaxf(vmax, 1e-20f);

    const float inv = 127.f / vmax;
    float q1f = rintf(s * inv);
    float r = fminf(fmaxf((s * inv - q1f) * 256.f, -128.f), 127.f);
    g_B1[o * 256 + k] = (char)(int)q1f;
    g_B2[o * 256 + k] = (char)(int)rintf(r);
    if (k == 0) g_sbB[o] = vmax / 127.f;
}

// ---------------------------------------------------------------------------
// kB_mma: persistent warp-specialized int8 pipeline. 512 threads, 1 CTA/SM.
//   B (two-level int8, 256x256) fully smem-resident, loaded once.
//   producers (warps 8-15): gather + per-row two-level int8 quantize of A.
//   consumers (warps 0-7): ldmatrix + mma.m16n8k32.s8, int32 accumulators.
// ---------------------------------------------------------------------------
#define AS1    272                      // A/B smem row stride (bytes)
#define A2_OFF 17408                    // A2 within buffer
#define SA_OFF 34816                    // per-node scale within buffer
#define A_BUF  35072                    // one A buffer (A1+A2+sa)
#define SM_B1  70144
#define SM_B2  (SM_B1 + 69632)          // 139776
#define SM_IX  (SM_B2 + 69632)          // 209408: 2 x 4352
#define SM_TOT (SM_IX + 2 * 64 * 17 * 4) // 218112 B -> 1 CTA/SM

#define BAR_FULL0  1
#define BAR_EMPTY0 3
#define BAR_PROD   5

#define BARSYNC(id, cnt) \
    asm volatile("bar.sync %0, %1;" :: "r"(id), "r"(cnt) : "memory")
#define BARARRIVE(id, cnt) \
    asm volatile("bar.arrive %0, %1;" :: "r"(id), "r"(cnt) : "memory")

__device__ __forceinline__ uint32_t s2u(const void* p) {
    uint32_t a;
    asm("{ .reg .u64 t; cvta.to.shared.u64 t, %1; cvt.u32.u64 %0, t; }"
        : "=r"(a) : "l"(p));
    return a;
}

#define LDSM4(r, addr) \
    asm volatile("ldmatrix.sync.aligned.m8n8.x4.shared.b16 {%0,%1,%2,%3}, [%4];" \
                 : "=r"((r)[0]), "=r"((r)[1]), "=r"((r)[2]), "=r"((r)[3]) \
                 : "r"(addr))

__device__ __forceinline__ void mma_s8(int* c, const uint32_t* a,
                                       uint32_t b0, uint32_t b1) {
    asm volatile(
        "mma.sync.aligned.m16n8k32.row.col.s32.s8.s8.s32 "
        "{%0,%1,%2,%3}, {%4,%5,%6,%7}, {%8,%9}, {%0,%1,%2,%3};"
        : "+r"(c[0]), "+r"(c[1]), "+r"(c[2]), "+r"(c[3])
        : "r"(a[0]), "r"(a[1]), "r"(a[2]), "r"(a[3]), "r"(b0), "r"(b1));
}

// two-level int8 quantize of 4 floats (|v*inv| <= 127 guaranteed by inv)
__device__ __forceinline__ void quant4(float4 v, float inv,
                                       uint32_t& w1, uint32_t& w2) {
    float f[4] = {v.x * inv, v.y * inv, v.z * inv, v.w * inv};
    uint32_t p1 = 0, p2 = 0;
    #pragma unroll
    for (int i = 0; i < 4; i++) {
        float q1f = rintf(f[i]);
        float r = fminf(fmaxf((f[i] - q1f) * 256.f, -128.f), 127.f);
        int q1 = (int)q1f, q2 = (int)rintf(r);
        p1 |= ((uint32_t)(q1 & 0xFF)) << (8 * i);
        p2 |= ((uint32_t)(q2 & 0xFF)) << (8 * i);
    }
    w1 = p1; w2 = p2;
}

__global__ void __launch_bounds__(512, 1)
kB_mma(const float* __restrict__ x, const int* __restrict__ nbr,
       const float* __restrict__ bias, float* __restrict__ out, int N)
{
    extern __shared__ char smem[];
    const uint32_t sb = s2u(smem);
    const int tid = threadIdx.x;
    const int lane = tid & 31;
    const int NT = (N + 63) >> 6;
    const int G = gridDim.x;

    // --- stage B (both levels) into smem ONCE (all 512 threads) ---
    {
        const uint4* s1 = (const uint4*)g_B1;
        const uint4* s2 = (const uint4*)g_B2;
        #pragma unroll
        for (int r = 0; r < 8; r++) {
            int c = tid + r * 512;           // 0..4095
            int o = c >> 4, k16 = c & 15;
            uint32_t d = (uint32_t)(o * AS1 + k16 * 16);
            *(uint4*)(smem + SM_B1 + d) = s1[c];
            *(uint4*)(smem + SM_B2 + d) = s2[c];
        }
    }
    __syncthreads();

    if (tid >= 256) {
        // ===================== PRODUCER (warps 8..15) =====================
        const int pw = (tid >> 5) - 8;       // 0..7
        const int ptid = tid - 256;          // 0..255
        int i = 0;
        for (int tile = blockIdx.x; tile < NT; tile += G, i++) {
            const int p = i & 1;
            const int nb = tile * 64;
            char* A1 = smem + p * A_BUF;
            char* A2 = A1 + A2_OFF;
            float* sAp = (float*)(A1 + SA_OFF);
            int* sIdx = (int*)(smem + SM_IX + p * 4352);

            #pragma unroll
            for (int r = 0; r < 4; r++) {
                int li = ptid + r * 256;     // 0..1023
                int nl = li >> 4, d = li & 15;
                int src = nb + nl; if (src >= N) src = N - 1;
                sIdx[nl * 17 + d] = nbr[(size_t)src * DDEG + d];
            }
            BARSYNC(BAR_PROD, 256);
            if (i >= 2) BARSYNC(BAR_EMPTY0 + p, 512);

            #pragma unroll 2
            for (int q = 0; q < 8; q++) {
                const int node = pw * 8 + q;
                const int* myidx = &sIdx[node * 17];
                int nsrc = nb + node; if (nsrc >= N) nsrc = N - 1;

                float4 a = make_float4(0.f, 0.f, 0.f, 0.f);
                #pragma unroll
                for (int d = 0; d < DDEG; d++) {
                    float4 v = *(const float4*)(x + (size_t)myidx[d] * FDIM + lane * 4);
                    a.x += v.x; a.y += v.y; a.z += v.z; a.w += v.w;
                }
                float4 sv = *(const float4*)(x + (size_t)nsrc * FDIM + lane * 4);
                a.x *= 0.0625f; a.y *= 0.0625f; a.z *= 0.0625f; a.w *= 0.0625f;

                // per-row absmax over all 256 k (self + nm)
                float lm = fmaxf(fmaxf(fmaxf(fabsf(sv.x), fabsf(sv.y)),
                                       fmaxf(fabsf(sv.z), fabsf(sv.w))),
                                 fmaxf(fmaxf(fabsf(a.x), fabsf(a.y)),
                                       fmaxf(fabsf(a.z), fabsf(a.w))));
                #pragma unroll
                for (int off = 16; off; off >>= 1)
                    lm = fmaxf(lm, __shfl_xor_sync(0xFFFFFFFFu, lm, off));
                lm = fmaxf(lm, 1e-20f);
                const float inv = 127.f / lm;

                uint32_t w1, w2;
                quant4(sv, inv, w1, w2);              // self: k in [0,128)
                *(uint32_t*)(A1 + node * AS1 + lane * 4) = w1;
                *(uint32_t*)(A2 + node * AS1 + lane * 4) = w2;
                quant4(a, inv, w1, w2);               // nm: k in [128,256)
                *(uint32_t*)(A1 + node * AS1 + 128 + lane * 4) = w1;
                *(uint32_t*)(A2 + node * AS1 + 128 + lane * 4) = w2;
                if (lane == 0) sAp[node] = lm / 127.f;
            }
            BARARRIVE(BAR_FULL0 + p, 512);
        }
    } else {
        // ===================== CONSUMER (warps 0..7) ======================
        const int w = tid >> 5;              // 0..7
        const int g = lane >> 2, t = lane & 3;
        const int m0 = (w >> 2) * 32;
        const int nw = (w & 3) * 16;

        const uint32_t aoff = (uint32_t)((lane & 15) * AS1 + (lane >> 4) * 16);
        const uint32_t boff = (uint32_t)(((lane & 7) + ((lane >> 4) << 3)) * AS1
                                         + ((lane >> 3) & 1) * 16);

        int i = 0;
        for (int tile = blockIdx.x; tile < NT; tile += G, i++) {
            const int p = i & 1;
            const int nb = tile * 64;
            const uint32_t aB1 = sb + (uint32_t)(p * A_BUF);
            const uint32_t aB2 = aB1 + A2_OFF;
            const float* sAp = (const float*)(smem + p * A_BUF + SA_OFF);

            BARSYNC(BAR_FULL0 + p, 512);

            const float sa00 = sAp[m0 + g],      sa01 = sAp[m0 + g + 8];
            const float sa10 = sAp[m0 + 16 + g], sa11 = sAp[m0 + 24 + g];

            #pragma unroll
            for (int ps = 0; ps < 4; ps++) {
                const int o0 = ps * 64 + nw;
                int S1[2][2][4], S2[2][2][4];
                #pragma unroll
                for (int mi = 0; mi < 2; mi++)
                    #pragma unroll
                    for (int j = 0; j < 2; j++)
                        #pragma unroll
                        for (int c = 0; c < 4; c++) { S1[mi][j][c] = 0; S2[mi][j][c] = 0; }

                #pragma unroll 2
                for (int kc = 0; kc < 8; kc++) {
                    const uint32_t kb = (uint32_t)(kc * 32);
                    uint32_t a1[2][4], a2[2][4];
                    #pragma unroll
                    for (int mi = 0; mi < 2; mi++) {
                        uint32_t base = (uint32_t)((m0 + mi * 16) * AS1) + kb + aoff;
                        LDSM4(a1[mi], aB1 + base);
                        LDSM4(a2[mi], aB2 + base);
                    }
                    uint32_t b1[4], b2[4];
                    {
                        uint32_t base = (uint32_t)(o0 * AS1) + kb + boff;
                        LDSM4(b1, sb + SM_B1 + base);
                        LDSM4(b2, sb + SM_B2 + base);
                    }
                    #pragma unroll
                    for (int j = 0; j < 2; j++)
                        #pragma unroll
                        for (int mi = 0; mi < 2; mi++) {
                            mma_s8(S1[mi][j], a1[mi], b1[2 * j], b1[2 * j + 1]);
                            mma_s8(S2[mi][j], a2[mi], b1[2 * j], b1[2 * j + 1]);
                            mma_s8(S2[mi][j], a1[mi], b2[2 * j], b2[2 * j + 1]);
                        }
                }

                if (ps == 3) BARARRIVE(BAR_EMPTY0 + p, 512);

                // epilogue: scale, +bias, ELU, store
                #pragma unroll
                for (int mi = 0; mi < 2; mi++) {
                    const int node0 = nb + m0 + mi * 16 + g;
                    const int node1 = node0 + 8;
                    const float saA = mi ? sa10 : sa00;
                    const float saB = mi ? sa11 : sa01;
                    #pragma unroll
                    for (int j = 0; j < 2; j++) {
                        const int o = o0 + j * 8 + 2 * t;
                        float2 bv = *(const float2*)&bias[o];
                        float2 sbv = *(const float2*)&g_sbB[o];
                        if (node0 < N) {
                            float c0 = (float)S1[mi][j][0] + (float)S2[mi][j][0] * 0.00390625f;
                            float c1 = (float)S1[mi][j][1] + (float)S2[mi][j][1] * 0.00390625f;
                            float t0 = saA * sbv.x * c0 + bv.x;
                            float t1 = saA * sbv.y * c1 + bv.y;
                            float2 vv;
                            vv.x = (t0 > 0.f) ? t0 : (__expf(t0) - 1.0f);
                            vv.y = (t1 > 0.f) ? t1 : (__expf(t1) - 1.0f);
                            *(float2*)(out + (size_t)node0 * ODIM + o) = vv;
                        }
                        if (node1 < N) {
                            float c2 = (float)S1[mi][j][2] + (float)S2[mi][j][2] * 0.00390625f;
                            float c3 = (float)S1[mi][j][3] + (float)S2[mi][j][3] * 0.00390625f;
                            float t2 = saB * sbv.x * c2 + bv.x;
                            float t3 = saB * sbv.y * c3 + bv.y;
                            float2 vv;
                            vv.x = (t2 > 0.f) ? t2 : (__expf(t2) - 1.0f);
                            vv.y = (t3 > 0.f) ? t3 : (__expf(t3) - 1.0f);
                            *(float2*)(out + (size_t)node1 * ODIM + o) = vv;
                        }
                    }
                }
            }
        }
    }
}

// ---------------------------------------------------------------------------
extern "C" void kernel_launch(void* const* d_in, const int* in_sizes, int n_in,
                              void* d_out, int out_size)
{
    const float* x    = (const float*)d_in[0];
    const int*   nbr  = (const int*)  d_in[1];
    const float* R    = (const float*)d_in[2];
    const float* Ws   = (const float*)d_in[3];
    const float* Wn   = (const float*)d_in[4];
    const float* bias = (const float*)d_in[5];
    const int N = in_sizes[0] / FDIM;

    static int nsm = 0;
    if (nsm == 0) {
        cudaDeviceGetAttribute(&nsm, cudaDevAttrMultiProcessorCount, 0);
        if (nsm <= 0) nsm = 148;
        cudaFuncSetAttribute(kB_mma, cudaFuncAttributeMaxDynamicSharedMemorySize, SM_TOT);
    }

    kA<<<dim3(2, 4, 2 * JS), 256>>>(R, Ws, Wn);
    kReduceQ<<<256, 256>>>();
    kB_mma<<<nsm, 512, SM_TOT>>>(x, nbr, bias, (float*)d_out, N);
}

// round 11
// speedup vs baseline: 2.4424x; 2.4424x over previous
#include <cuda_runtime.h>
#include <cuda_fp16.h>
#include <math.h>
#include <stdint.h>

// ---------------------------------------------------------------------------
#define FDIM 128
#define DDEG 16
#define KH   2048
#define ODIM 256
#define JS   16
#define JCH  (KH/JS)

// Scratch (device globals; no allocation allowed)
__device__ float g_Mpart[JS][2][FDIM][ODIM];        // 4 MB partials
__device__ __align__(16) __half g_Bh[ODIM * 256];   // B[o][k] single fp16

// ---------------------------------------------------------------------------
// Kernel A: partial M[m][f][o] over a 128-wide j chunk (~14us)
// ---------------------------------------------------------------------------
__global__ void __launch_bounds__(256)
kA(const float* __restrict__ R, const float* __restrict__ Ws,
   const float* __restrict__ Wn)
{
    __shared__ float sA[32][68];
    __shared__ float sB[32][68];

    const int ft = blockIdx.x, ot = blockIdx.y, mz = blockIdx.z;
    const int m = mz / JS, jc = mz % JS;
    const float* __restrict__ W = m ? Wn : Ws;
    const int f0 = ft * 64, o0 = ot * 64;
    const int jbase = jc * JCH;
    const int kk = jbase >> 8, hb = jbase & 255;
    const int tid = threadIdx.x, tx = tid & 15, ty = tid >> 4;

    float acc[4][4];
    #pragma unroll
    for (int i = 0; i < 4; i++)
        #pragma unroll
        for (int j = 0; j < 4; j++) acc[i][j] = 0.f;

    for (int jt = 0; jt < JCH; jt += 32) {
        #pragma unroll
        for (int r = 0; r < 2; r++) {
            int li = tid + r * 256;
            int f_l = li >> 3, jj = (li & 7) * 4;
            float4 a4 = *(const float4*)(R + (size_t)kk * (FDIM * 256)
                                           + (size_t)(f0 + f_l) * 256 + hb + jt + jj);
            sA[jj + 0][f_l] = a4.x; sA[jj + 1][f_l] = a4.y;
            sA[jj + 2][f_l] = a4.z; sA[jj + 3][f_l] = a4.w;
        }
        #pragma unroll
        for (int r = 0; r < 2; r++) {
            int li = tid + r * 256;
            int o_l = li >> 3, jj = (li & 7) * 4;
            float4 b4 = *(const float4*)(W + (size_t)(o0 + o_l) * KH + jbase + jt + jj);
            sB[jj + 0][o_l] = b4.x; sB[jj + 1][o_l] = b4.y;
            sB[jj + 2][o_l] = b4.z; sB[jj + 3][o_l] = b4.w;
        }
        __syncthreads();
        #pragma unroll
        for (int jj = 0; jj < 32; jj++) {
            float4 a4 = *(const float4*)&sA[jj][ty * 4];
            float4 b4 = *(const float4*)&sB[jj][tx * 4];
            float a[4] = {a4.x, a4.y, a4.z, a4.w};
            float b[4] = {b4.x, b4.y, b4.z, b4.w};
            #pragma unroll
            for (int i = 0; i < 4; i++)
                #pragma unroll
                for (int j = 0; j < 4; j++) acc[i][j] += a[i] * b[j];
        }
        __syncthreads();
    }
    float* outp = &g_Mpart[jc][m][0][0];
    #pragma unroll
    for (int i = 0; i < 4; i++) {
        float4 v = make_float4(acc[i][0], acc[i][1], acc[i][2], acc[i][3]);
        *(float4*)(outp + (size_t)(f0 + ty * 4 + i) * ODIM + o0 + tx * 4) = v;
    }
}

// Reduce partials -> single fp16 B[o][k], k = m*128+f.
__global__ void __launch_bounds__(256)
kReduce()
{
    int i = blockIdx.x * 256 + threadIdx.x;  // [m][f][o]
    const float* p = (const float*)g_Mpart;
    float s = 0.f;
    #pragma unroll
    for (int q = 0; q < JS; q++) s += p[(size_t)q * 2 * FDIM * ODIM + i];
    int m = i >> 15, f = (i >> 8) & 127, o = i & 255;
    int k = m * 128 + f;
    g_Bh[o * 256 + k] = __float2half_rn(s);
}

// ---------------------------------------------------------------------------
// kB_mma: persistent warp-specialized pipeline, 2-pass split-fp16.
//   warps 0-7  (consumers): ldmatrix + mma m16n8k16 f16 (Ahi*B + Alo*B).
//   warps 8-15 (producers): warp-cooperative gather into double-buffered A.
// ---------------------------------------------------------------------------
#define AS 264   // A smem row stride (fp16): 256 k + 8 pad, conflict-free LDSM
#define BS2 40   // B chunk smem row stride (fp16)

#define ALO    (64 * AS * 2)                   // 33792: Al within A buffer
#define A_BUF  (2 * 64 * AS * 2)               // 67584 per buffer (Ah+Al)
#define SM_BB  (2 * A_BUF)                     // 135168: 2 x 10240 B chunks
#define SM_IX  (SM_BB + 2 * 128 * BS2 * 2)     // 155648: 2 x 4352
#define SM_TOT (SM_IX + 2 * 64 * 17 * 4)       // 164352 B -> 1 CTA/SM

#define BBUF(b) (SM_BB + (b) * (128 * BS2 * 2))

// named barrier ids
#define BAR_FULL0  1
#define BAR_EMPTY0 3
#define BAR_PROD   5
#define BAR_CONS   6

#define BARSYNC(id, cnt) \
    asm volatile("bar.sync %0, %1;" :: "r"(id), "r"(cnt) : "memory")
#define BARARRIVE(id, cnt) \
    asm volatile("bar.arrive %0, %1;" :: "r"(id), "r"(cnt) : "memory")

__device__ __forceinline__ uint32_t s2u(const void* p) {
    uint32_t a;
    asm("{ .reg .u64 t; cvta.to.shared.u64 t, %1; cvt.u32.u64 %0, t; }"
        : "=r"(a) : "l"(p));
    return a;
}

#define CP16(s, g) \
    asm volatile("cp.async.cg.shared.global [%0], [%1], 16;" :: "r"(s), "l"(g))
#define CP_COMMIT() asm volatile("cp.async.commit_group;" ::: "memory")
#define CP_WAIT1()  asm volatile("cp.async.wait_group 1;" ::: "memory")
#define CP_WAIT0()  asm volatile("cp.async.wait_group 0;" ::: "memory")

#define LDSM4(r, addr) \
    asm volatile("ldmatrix.sync.aligned.m8n8.x4.shared.b16 {%0,%1,%2,%3}, [%4];" \
                 : "=r"((r)[0]), "=r"((r)[1]), "=r"((r)[2]), "=r"((r)[3]) \
                 : "r"(addr))

__device__ __forceinline__ void mma_f16(float* c, const uint32_t* a,
                                        uint32_t b0, uint32_t b1) {
    asm volatile(
        "mma.sync.aligned.m16n8k16.row.col.f32.f16.f16.f32 "
        "{%0,%1,%2,%3}, {%4,%5,%6,%7}, {%8,%9}, {%0,%1,%2,%3};"
        : "+f"(c[0]), "+f"(c[1]), "+f"(c[2]), "+f"(c[3])
        : "r"(a[0]), "r"(a[1]), "r"(a[2]), "r"(a[3]), "r"(b0), "r"(b1));
}

// pack 4 scaled floats into split-fp16 hi/lo and store 8B to each array
__device__ __forceinline__ void put4(__half* Ah, __half* Al,
                                     int off, float4 v, float s) {
    float f0 = v.x * s, f1 = v.y * s, f2 = v.z * s, f3 = v.w * s;
    __half2 h01 = __floats2half2_rn(f0, f1);
    __half2 h23 = __floats2half2_rn(f2, f3);
    float2 g01 = __half22float2(h01), g23 = __half22float2(h23);
    __half2 l01 = __floats2half2_rn(f0 - g01.x, f1 - g01.y);
    __half2 l23 = __floats2half2_rn(f2 - g23.x, f3 - g23.y);
    uint2 hp, lp;
    hp.x = *(uint32_t*)&h01; hp.y = *(uint32_t*)&h23;
    lp.x = *(uint32_t*)&l01; lp.y = *(uint32_t*)&l23;
    *(uint2*)&Ah[off] = hp;
    *(uint2*)&Al[off] = lp;
}

// async-stage one 32-k B chunk into buffer b (256 consumer threads)
__device__ __forceinline__ void stageB(uint32_t sb, int b, int half, int kc, int ctid) {
    const uint32_t d = sb + BBUF(b);
    #pragma unroll
    for (int r = 0; r < 2; r++) {
        int li = ctid + r * 256;         // 0..511
        int row = li >> 2, seg = li & 3;
        size_t gsrc = (size_t)(half * 128 + row) * 256 + kc * 32 + seg * 8;
        uint32_t sa = (uint32_t)(row * (BS2 * 2) + seg * 16);
        CP16(d + sa, (const char*)&g_Bh[gsrc]);
    }
}

__global__ void __launch_bounds__(512, 1)
kB_mma(const float* __restrict__ x, const int* __restrict__ nbr,
       const float* __restrict__ bias, float* __restrict__ out, int N)
{
    extern __shared__ char smem[];
    const uint32_t sb = s2u(smem);
    const int tid = threadIdx.x;
    const int lane = tid & 31;
    const int NT = (N + 63) >> 6;
    const int G = gridDim.x;

    if (tid >= 256) {
        // ===================== PRODUCER (warps 8..15) =====================
        const int pw = (tid >> 5) - 8;       // 0..7
        const int ptid = tid - 256;          // 0..255
        int i = 0;
        for (int tile = blockIdx.x; tile < NT; tile += G, i++) {
            const int p = i & 1;
            const int nb = tile * 64;
            __half* Ah = (__half*)(smem + p * A_BUF);
            __half* Al = (__half*)(smem + p * A_BUF + ALO);
            int* sIdx = (int*)(smem + SM_IX + p * 4352);

            #pragma unroll
            for (int r = 0; r < 4; r++) {
                int li = ptid + r * 256;     // 0..1023
                int nl = li >> 4, d = li & 15;
                int src = nb + nl; if (src >= N) src = N - 1;
                sIdx[nl * 17 + d] = nbr[(size_t)src * DDEG + d];
            }
            BARSYNC(BAR_PROD, 256);          // idx visible to all producers
            if (i >= 2) BARSYNC(BAR_EMPTY0 + p, 512);  // buffer free?

            #pragma unroll 2
            for (int q = 0; q < 8; q++) {
                const int node = pw * 8 + q;
                const int* myidx = &sIdx[node * 17];
                int nsrc = nb + node; if (nsrc >= N) nsrc = N - 1;

                float4 a = make_float4(0.f, 0.f, 0.f, 0.f);
                #pragma unroll
                for (int d = 0; d < DDEG; d++) {
                    float4 v = *(const float4*)(x + (size_t)myidx[d] * FDIM + lane * 4);
                    a.x += v.x; a.y += v.y; a.z += v.z; a.w += v.w;
                }
                float4 sv = *(const float4*)(x + (size_t)nsrc * FDIM + lane * 4);

                put4(Ah, Al, node * AS + 128 + lane * 4, a, 0.0625f); // nm
                put4(Ah, Al, node * AS + lane * 4, sv, 1.0f);         // self
            }
            BARARRIVE(BAR_FULL0 + p, 512);   // A[p] full
        }
    } else {
        // ===================== CONSUMER (warps 0..7) ======================
        const int w = tid >> 5;              // 0..7
        const int ctid = tid;                // 0..255
        const int g = lane >> 2, t = lane & 3;
        const int m0 = (w >> 2) * 32;
        const int n0 = (w & 3) * 32;

        const uint32_t aoff = (uint32_t)(((lane & 15) * AS + ((lane >> 4) << 3)) * 2);
        const uint32_t boff = (uint32_t)((((lane & 7) + ((lane >> 4) << 3)) * BS2
                                          + (((lane >> 3) & 1) << 3)) * 2);

        // prefetch B chunk 0 of first tile
        if (blockIdx.x < NT) { stageB(sb, 0, 0, 0, ctid); CP_COMMIT(); }

        int i = 0;
        for (int tile = blockIdx.x; tile < NT; tile += G, i++) {
            const int p = i & 1;
            const int nb = tile * 64;
            const uint32_t aBase = sb + (uint32_t)(p * A_BUF);
            const bool moreTiles = (tile + G) < NT;

            BARSYNC(BAR_FULL0 + p, 512);     // wait A[p]

            #pragma unroll
            for (int half = 0; half < 2; half++) {
                float acc[2][4][4];
                #pragma unroll
                for (int mi = 0; mi < 2; mi++)
                    #pragma unroll
                    for (int j = 0; j < 4; j++)
                        #pragma unroll
                        for (int c = 0; c < 4; c++) acc[mi][j][c] = 0.f;

                for (int kc = 0; kc < 8; kc++) {
                    const int cc = half * 8 + kc;
                    if (cc < 15) {
                        const int nc = cc + 1;
                        stageB(sb, nc & 1, nc >> 3, nc & 7, ctid);
                        CP_COMMIT();
                        CP_WAIT1();          // chunk cc resident
                    } else if (moreTiles) {
                        stageB(sb, 0, 0, 0, ctid);   // chunk0 of next tile
                        CP_COMMIT();
                        CP_WAIT1();
                    } else {
                        CP_WAIT0();
                    }
                    BARSYNC(BAR_CONS, 256);

                    const uint32_t bB = sb + BBUF(cc & 1);

                    #pragma unroll
                    for (int kk = 0; kk < 2; kk++) {
                        const int ka = kc * 32 + kk * 16;
                        uint32_t ah[2][4], al[2][4];
                        #pragma unroll
                        for (int mi = 0; mi < 2; mi++) {
                            uint32_t base = (uint32_t)(((m0 + mi * 16) * AS + ka) * 2) + aoff;
                            LDSM4(ah[mi], aBase + base);
                            LDSM4(al[mi], aBase + (uint32_t)ALO + base);
                        }
                        uint32_t bh[4][2];
                        #pragma unroll
                        for (int jp = 0; jp < 2; jp++) {
                            uint32_t base = (uint32_t)(((n0 + jp * 16) * BS2 + kk * 16) * 2) + boff;
                            uint32_t tm[4];
                            LDSM4(tm, bB + base);
                            bh[2 * jp][0] = tm[0]; bh[2 * jp][1] = tm[1];
                            bh[2 * jp + 1][0] = tm[2]; bh[2 * jp + 1][1] = tm[3];
                        }
                        #pragma unroll
                        for (int j = 0; j < 4; j++)
                            #pragma unroll
                            for (int mi = 0; mi < 2; mi++) {
                                mma_f16(acc[mi][j], ah[mi], bh[j][0], bh[j][1]); // hi*B
                                mma_f16(acc[mi][j], al[mi], bh[j][0], bh[j][1]); // lo*B
                            }
                    }
                    BARSYNC(BAR_CONS, 256);
                }

                if (half == 1) BARARRIVE(BAR_EMPTY0 + p, 512);  // A[p] free

                // epilogue for this 128-wide output half (fast ELU)
                #pragma unroll
                for (int mi = 0; mi < 2; mi++) {
                    int node0 = nb + m0 + mi * 16 + g;
                    int node1 = node0 + 8;
                    #pragma unroll
                    for (int j = 0; j < 4; j++) {
                        int o = half * 128 + n0 + j * 8 + 2 * t;
                        float2 bv = *(const float2*)&bias[o];
                        if (node0 < N) {
                            float t0 = acc[mi][j][0] + bv.x;
                            float t1 = acc[mi][j][1] + bv.y;
                            float2 v;
                            v.x = (t0 > 0.f) ? t0 : (__expf(t0) - 1.0f);
                            v.y = (t1 > 0.f) ? t1 : (__expf(t1) - 1.0f);
                            *(float2*)(out + (size_t)node0 * ODIM + o) = v;
                        }
                        if (node1 < N) {
                            float t2 = acc[mi][j][2] + bv.x;
                            float t3 = acc[mi][j][3] + bv.y;
                            float2 v;
                            v.x = (t2 > 0.f) ? t2 : (__expf(t2) - 1.0f);
                            v.y = (t3 > 0.f) ? t3 : (__expf(t3) - 1.0f);
                            *(float2*)(out + (size_t)node1 * ODIM + o) = v;
                        }
                    }
                }
            }
        }
    }
}

// ---------------------------------------------------------------------------
extern "C" void kernel_launch(void* const* d_in, const int* in_sizes, int n_in,
                              void* d_out, int out_size)
{
    const float* x    = (const float*)d_in[0];
    const int*   nbr  = (const int*)  d_in[1];
    const float* R    = (const float*)d_in[2];
    const float* Ws   = (const float*)d_in[3];
    const float* Wn   = (const float*)d_in[4];
    const float* bias = (const float*)d_in[5];
    const int N = in_sizes[0] / FDIM;

    static int nsm = 0;
    if (nsm == 0) {
        cudaDeviceGetAttribute(&nsm, cudaDevAttrMultiProcessorCount, 0);
        if (nsm <= 0) nsm = 148;
        cudaFuncSetAttribute(kB_mma, cudaFuncAttributeMaxDynamicSharedMemorySize, SM_TOT);
    }

    kA<<<dim3(2, 4, 2 * JS), 256>>>(R, Ws, Wn);
    kReduce<<<(2 * FDIM * ODIM) / 256, 256>>>();
    kB_mma<<<nsm, 512, SM_TOT>>>(x, nbr, bias, (float*)d_out, N);
}

// round 12
// speedup vs baseline: 2.7015x; 1.1061x over previous
#include <cuda_runtime.h>
#include <cuda_fp16.h>
#include <math.h>
#include <stdint.h>

// ---------------------------------------------------------------------------
#define FDIM 128
#define DDEG 16
#define KH   2048
#define ODIM 256
#define JS   16
#define JCH  (KH/JS)

// Scratch (device globals; no allocation allowed)
__device__ float g_Mpart[JS][2][FDIM][ODIM];        // 4 MB partials
__device__ __align__(16) __half g_Bh[ODIM * 256];   // B[o][k] single fp16

// ---------------------------------------------------------------------------
// Kernel A: partial M[m][f][o] over a 128-wide j chunk (~14us)
// ---------------------------------------------------------------------------
__global__ void __launch_bounds__(256)
kA(const float* __restrict__ R, const float* __restrict__ Ws,
   const float* __restrict__ Wn)
{
    __shared__ float sA[32][68];
    __shared__ float sB[32][68];

    const int ft = blockIdx.x, ot = blockIdx.y, mz = blockIdx.z;
    const int m = mz / JS, jc = mz % JS;
    const float* __restrict__ W = m ? Wn : Ws;
    const int f0 = ft * 64, o0 = ot * 64;
    const int jbase = jc * JCH;
    const int kk = jbase >> 8, hb = jbase & 255;
    const int tid = threadIdx.x, tx = tid & 15, ty = tid >> 4;

    float acc[4][4];
    #pragma unroll
    for (int i = 0; i < 4; i++)
        #pragma unroll
        for (int j = 0; j < 4; j++) acc[i][j] = 0.f;

    for (int jt = 0; jt < JCH; jt += 32) {
        #pragma unroll
        for (int r = 0; r < 2; r++) {
            int li = tid + r * 256;
            int f_l = li >> 3, jj = (li & 7) * 4;
            float4 a4 = *(const float4*)(R + (size_t)kk * (FDIM * 256)
                                           + (size_t)(f0 + f_l) * 256 + hb + jt + jj);
            sA[jj + 0][f_l] = a4.x; sA[jj + 1][f_l] = a4.y;
            sA[jj + 2][f_l] = a4.z; sA[jj + 3][f_l] = a4.w;
        }
        #pragma unroll
        for (int r = 0; r < 2; r++) {
            int li = tid + r * 256;
            int o_l = li >> 3, jj = (li & 7) * 4;
            float4 b4 = *(const float4*)(W + (size_t)(o0 + o_l) * KH + jbase + jt + jj);
            sB[jj + 0][o_l] = b4.x; sB[jj + 1][o_l] = b4.y;
            sB[jj + 2][o_l] = b4.z; sB[jj + 3][o_l] = b4.w;
        }
        __syncthreads();
        #pragma unroll
        for (int jj = 0; jj < 32; jj++) {
            float4 a4 = *(const float4*)&sA[jj][ty * 4];
            float4 b4 = *(const float4*)&sB[jj][tx * 4];
            float a[4] = {a4.x, a4.y, a4.z, a4.w};
            float b[4] = {b4.x, b4.y, b4.z, b4.w};
            #pragma unroll
            for (int i = 0; i < 4; i++)
                #pragma unroll
                for (int j = 0; j < 4; j++) acc[i][j] += a[i] * b[j];
        }
        __syncthreads();
    }
    float* outp = &g_Mpart[jc][m][0][0];
    #pragma unroll
    for (int i = 0; i < 4; i++) {
        float4 v = make_float4(acc[i][0], acc[i][1], acc[i][2], acc[i][3]);
        *(float4*)(outp + (size_t)(f0 + ty * 4 + i) * ODIM + o0 + tx * 4) = v;
    }
}

// Reduce partials -> single fp16 B[o][k], k = m*128+f.
__global__ void __launch_bounds__(256)
kReduce()
{
    int i = blockIdx.x * 256 + threadIdx.x;  // [m][f][o]
    const float* p = (const float*)g_Mpart;
    float s = 0.f;
    #pragma unroll
    for (int q = 0; q < JS; q++) s += p[(size_t)q * 2 * FDIM * ODIM + i];
    int m = i >> 15, f = (i >> 8) & 127, o = i & 255;
    int k = m * 128 + f;
    g_Bh[o * 256 + k] = __float2half_rn(s);
}

// ---------------------------------------------------------------------------
// kB_mma: persistent warp-specialized pipeline, 1-pass fp16, B smem-resident.
//   warps 0-7  (consumers): pure ldmatrix + mma m16n8k16 f16 + epilogue.
//   warps 8-15 (producers): warp-cooperative gather into double-buffered A.
// ---------------------------------------------------------------------------
#define AS 264   // row stride (fp16 elems): 256 k + 8 pad, conflict-free LDSM

#define A_BUF  (64 * AS * 2)                   // 33792 per buffer (fp16 A)
#define SM_B   (2 * A_BUF)                     // 67584
#define SM_IX  (SM_B + 256 * AS * 2)           // 202752: 2 x 4352
#define SM_TOT (SM_IX + 2 * 64 * 17 * 4)       // 211456 B -> 1 CTA/SM

// named barrier ids
#define BAR_FULL0  1
#define BAR_EMPTY0 3
#define BAR_PROD   5

#define BARSYNC(id, cnt) \
    asm volatile("bar.sync %0, %1;" :: "r"(id), "r"(cnt) : "memory")
#define BARARRIVE(id, cnt) \
    asm volatile("bar.arrive %0, %1;" :: "r"(id), "r"(cnt) : "memory")

__device__ __forceinline__ uint32_t s2u(const void* p) {
    uint32_t a;
    asm("{ .reg .u64 t; cvta.to.shared.u64 t, %1; cvt.u32.u64 %0, t; }"
        : "=r"(a) : "l"(p));
    return a;
}

#define LDSM4(r, addr) \
    asm volatile("ldmatrix.sync.aligned.m8n8.x4.shared.b16 {%0,%1,%2,%3}, [%4];" \
                 : "=r"((r)[0]), "=r"((r)[1]), "=r"((r)[2]), "=r"((r)[3]) \
                 : "r"(addr))

__device__ __forceinline__ void mma_f16(float* c, const uint32_t* a,
                                        uint32_t b0, uint32_t b1) {
    asm volatile(
        "mma.sync.aligned.m16n8k16.row.col.f32.f16.f16.f32 "
        "{%0,%1,%2,%3}, {%4,%5,%6,%7}, {%8,%9}, {%0,%1,%2,%3};"
        : "+f"(c[0]), "+f"(c[1]), "+f"(c[2]), "+f"(c[3])
        : "r"(a[0]), "r"(a[1]), "r"(a[2]), "r"(a[3]), "r"(b0), "r"(b1));
}

// pack 4 scaled floats into fp16 and store 8B
__device__ __forceinline__ void put4(__half* Ah, int off, float4 v, float s) {
    __half2 h01 = __floats2half2_rn(v.x * s, v.y * s);
    __half2 h23 = __floats2half2_rn(v.z * s, v.w * s);
    uint2 hp;
    hp.x = *(uint32_t*)&h01; hp.y = *(uint32_t*)&h23;
    *(uint2*)&Ah[off] = hp;
}

__global__ void __launch_bounds__(512, 1)
kB_mma(const float* __restrict__ x, const int* __restrict__ nbr,
       const float* __restrict__ bias, float* __restrict__ out, int N)
{
    extern __shared__ char smem[];
    const uint32_t sb = s2u(smem);
    const int tid = threadIdx.x;
    const int lane = tid & 31;
    const int NT = (N + 63) >> 6;
    const int G = gridDim.x;

    // --- stage B [256 o][256 k] fp16 into smem ONCE (all 512 threads) ---
    {
        const uint4* src = (const uint4*)g_Bh;
        #pragma unroll
        for (int r = 0; r < 16; r++) {
            int c = tid + r * 512;           // 0..8191 (16B units)
            int o = c >> 5, k8 = c & 31;     // 32 x 16B per 256-k row
            *(uint4*)(smem + SM_B + (uint32_t)(o * (AS * 2) + k8 * 16)) = src[c];
        }
    }
    __syncthreads();

    if (tid >= 256) {
        // ===================== PRODUCER (warps 8..15) =====================
        const int pw = (tid >> 5) - 8;       // 0..7
        const int ptid = tid - 256;          // 0..255
        int i = 0;
        for (int tile = blockIdx.x; tile < NT; tile += G, i++) {
            const int p = i & 1;
            const int nb = tile * 64;
            __half* Ah = (__half*)(smem + p * A_BUF);
            int* sIdx = (int*)(smem + SM_IX + p * 4352);

            #pragma unroll
            for (int r = 0; r < 4; r++) {
                int li = ptid + r * 256;     // 0..1023
                int nl = li >> 4, d = li & 15;
                int src = nb + nl; if (src >= N) src = N - 1;
                sIdx[nl * 17 + d] = nbr[(size_t)src * DDEG + d];
            }
            BARSYNC(BAR_PROD, 256);          // idx visible to all producers
            if (i >= 2) BARSYNC(BAR_EMPTY0 + p, 512);  // buffer free?

            #pragma unroll 2
            for (int q = 0; q < 8; q++) {
                const int node = pw * 8 + q;
                const int* myidx = &sIdx[node * 17];
                int nsrc = nb + node; if (nsrc >= N) nsrc = N - 1;

                float4 a = make_float4(0.f, 0.f, 0.f, 0.f);
                #pragma unroll
                for (int d = 0; d < DDEG; d++) {
                    float4 v = *(const float4*)(x + (size_t)myidx[d] * FDIM + lane * 4);
                    a.x += v.x; a.y += v.y; a.z += v.z; a.w += v.w;
                }
                float4 sv = *(const float4*)(x + (size_t)nsrc * FDIM + lane * 4);

                put4(Ah, node * AS + 128 + lane * 4, a, 0.0625f); // nm
                put4(Ah, node * AS + lane * 4, sv, 1.0f);         // self
            }
            BARARRIVE(BAR_FULL0 + p, 512);   // A[p] full
        }
    } else {
        // ===================== CONSUMER (warps 0..7) ======================
        const int w = tid >> 5;              // 0..7
        const int g = lane >> 2, t = lane & 3;
        const int m0 = (w >> 2) * 32;
        const int n0 = (w & 3) * 32;

        const uint32_t aoff = (uint32_t)(((lane & 15) * AS + ((lane >> 4) << 3)) * 2);
        const uint32_t boff = (uint32_t)((((lane & 7) + ((lane >> 4) << 3)) * AS
                                          + (((lane >> 3) & 1) << 3)) * 2);

        int i = 0;
        for (int tile = blockIdx.x; tile < NT; tile += G, i++) {
            const int p = i & 1;
            const int nb = tile * 64;
            const uint32_t aBase = sb + (uint32_t)(p * A_BUF);

            BARSYNC(BAR_FULL0 + p, 512);     // wait A[p]

            #pragma unroll
            for (int oh = 0; oh < 2; oh++) {
                float acc[2][4][4];
                #pragma unroll
                for (int mi = 0; mi < 2; mi++)
                    #pragma unroll
                    for (int j = 0; j < 4; j++)
                        #pragma unroll
                        for (int c = 0; c < 4; c++) acc[mi][j][c] = 0.f;

                const int o0 = oh * 128 + n0;

                #pragma unroll 4
                for (int ks = 0; ks < 16; ks++) {
                    const uint32_t kb = (uint32_t)(ks * 16 * 2);
                    uint32_t ah[2][4];
                    #pragma unroll
                    for (int mi = 0; mi < 2; mi++) {
                        uint32_t base = (uint32_t)((m0 + mi * 16) * AS * 2) + kb + aoff;
                        LDSM4(ah[mi], aBase + base);
                    }
                    uint32_t bh[4][2];
                    #pragma unroll
                    for (int jp = 0; jp < 2; jp++) {
                        uint32_t base = (uint32_t)((o0 + jp * 16) * AS * 2) + kb + boff;
                        uint32_t tm[4];
                        LDSM4(tm, sb + SM_B + base);
                        bh[2 * jp][0] = tm[0]; bh[2 * jp][1] = tm[1];
                        bh[2 * jp + 1][0] = tm[2]; bh[2 * jp + 1][1] = tm[3];
                    }
                    #pragma unroll
                    for (int j = 0; j < 4; j++)
                        #pragma unroll
                        for (int mi = 0; mi < 2; mi++)
                            mma_f16(acc[mi][j], ah[mi], bh[j][0], bh[j][1]);
                }

                if (oh == 1) BARARRIVE(BAR_EMPTY0 + p, 512);  // A[p] free

                // epilogue (fast ELU)
                #pragma unroll
                for (int mi = 0; mi < 2; mi++) {
                    int node0 = nb + m0 + mi * 16 + g;
                    int node1 = node0 + 8;
                    #pragma unroll
                    for (int j = 0; j < 4; j++) {
                        int o = o0 + j * 8 + 2 * t;
                        float2 bv = *(const float2*)&bias[o];
                        if (node0 < N) {
                            float t0 = acc[mi][j][0] + bv.x;
                            float t1 = acc[mi][j][1] + bv.y;
                            float2 v;
                            v.x = (t0 > 0.f) ? t0 : (__expf(t0) - 1.0f);
                            v.y = (t1 > 0.f) ? t1 : (__expf(t1) - 1.0f);
                            *(float2*)(out + (size_t)node0 * ODIM + o) = v;
                        }
                        if (node1 < N) {
                            float t2 = acc[mi][j][2] + bv.x;
                            float t3 = acc[mi][j][3] + bv.y;
                            float2 v;
                            v.x = (t2 > 0.f) ? t2 : (__expf(t2) - 1.0f);
                            v.y = (t3 > 0.f) ? t3 : (__expf(t3) - 1.0f);
                            *(float2*)(out + (size_t)node1 * ODIM + o) = v;
                        }
                    }
                }
            }
        }
    }
}

// ---------------------------------------------------------------------------
extern "C" void kernel_launch(void* const* d_in, const int* in_sizes, int n_in,
                              void* d_out, int out_size)
{
    const float* x    = (const float*)d_in[0];
    const int*   nbr  = (const int*)  d_in[1];
    const float* R    = (const float*)d_in[2];
    const float* Ws   = (const float*)d_in[3];
    const float* Wn   = (const float*)d_in[4];
    const float* bias = (const float*)d_in[5];
    const int N = in_sizes[0] / FDIM;

    static int nsm = 0;
    if (nsm == 0) {
        cudaDeviceGetAttribute(&nsm, cudaDevAttrMultiProcessorCount, 0);
        if (nsm <= 0) nsm = 148;
        cudaFuncSetAttribute(kB_mma, cudaFuncAttributeMaxDynamicSharedMemorySize, SM_TOT);
    }

    kA<<<dim3(2, 4, 2 * JS), 256>>>(R, Ws, Wn);
    kReduce<<<(2 * FDIM * ODIM) / 256, 256>>>();
    kB_mma<<<nsm, 512, SM_TOT>>>(x, nbr, bias, (float*)d_out, N);
}